// round 17
// baseline (speedup 1.0000x reference)
#include <cuda_runtime.h>
#include <cuda_bf16.h>

#define BN_EPS 1e-5f
#define MAX_E 1000000

// ---- device scratch (allocation-free) ----
static __device__ __align__(128) __nv_bfloat16 g_hh[(size_t)MAX_E * 64];  // h hi
static __device__ __align__(128) __nv_bfloat16 g_hl[(size_t)MAX_E * 64];  // h lo
static __device__ __align__(128) __nv_bfloat16 g_W1s[8 * 4096];  // [chunk][hi|lo][4096] swizzled
static __device__ __align__(128) __nv_bfloat16 g_W2s[2 * 4096];
static __device__ __align__(128) __nv_bfloat16 g_W3s[2 * 4096];
static __device__ float g_bf2[64], g_bf3[64];
static __device__ float g_sum[3][64], g_sq[3][64], g_s3[64], g_t3[64];
static __device__ int   g_is64;

// ---- helpers ----
__device__ __forceinline__ unsigned smem_u32(const void* p) {
    return (unsigned)__cvta_generic_to_shared(p);
}
__device__ __forceinline__ void cp16(unsigned dst, const void* src) {
    asm volatile("cp.async.cg.shared.global [%0], [%1], 16;" :: "r"(dst), "l"(src));
}
__device__ __forceinline__ void cp_commit() { asm volatile("cp.async.commit_group;" ::: "memory"); }
template <int N> __device__ __forceinline__ void cp_wait() {
    asm volatile("cp.async.wait_group %0;" :: "n"(N) : "memory");
}
__device__ __forceinline__ unsigned swz(unsigned o) { return o ^ ((o >> 3) & 0x70); }
__device__ __forceinline__ unsigned packbf(float lo, float hi) {
    unsigned r;
    asm("cvt.rn.bf16x2.f32 %0, %1, %2;" : "=r"(r) : "f"(hi), "f"(lo));  // upper=hi word
    return r;
}
__device__ __forceinline__ void ldsm4(unsigned* r, unsigned a) {
    asm volatile("ldmatrix.sync.aligned.m8n8.x4.shared.b16 {%0,%1,%2,%3}, [%4];"
                 : "=r"(r[0]), "=r"(r[1]), "=r"(r[2]), "=r"(r[3]) : "r"(a));
}
__device__ __forceinline__ void mma16816(float* c, const unsigned* a, const unsigned* b) {
    asm volatile("mma.sync.aligned.m16n8k16.row.col.f32.bf16.bf16.f32 "
                 "{%0,%1,%2,%3}, {%4,%5,%6,%7}, {%8,%9}, {%0,%1,%2,%3};"
                 : "+f"(c[0]), "+f"(c[1]), "+f"(c[2]), "+f"(c[3])
                 : "r"(a[0]), "r"(a[1]), "r"(a[2]), "r"(a[3]), "r"(b[0]), "r"(b[1]));
}
__device__ __forceinline__ long long load_bidx(const void* b, int row, int G) {
    long long v = g_is64 ? ((const long long*)b)[row] : (long long)((const int*)b)[row];
    if (v < 0) v = 0;
    if (v >= (long long)G) v = G - 1;
    return v;
}

// ---- prep: zero stats, dtype probe, W1 -> split+swizzled tiles ----
__global__ void prep_kernel(const float* __restrict__ W1, const void* __restrict__ batch,
                            int E, int G) {
    if (blockIdx.x == 0) {
        float* s = &g_sum[0][0];
        float* q = &g_sq[0][0];
        for (int i = threadIdx.x; i < 192; i += blockDim.x) { s[i] = 0.f; q[i] = 0.f; }
        if (threadIdx.x == 0) {
            const long long* b64 = (const long long*)batch;
            int n = (E < 64) ? E : 64, ok = 1;
            for (int i = 0; i < n; i++) {
                long long v = b64[i];
                if (v < 0 || v >= (long long)G) { ok = 0; break; }
            }
            g_is64 = ok;
        }
    }
    int tid = blockIdx.x * blockDim.x + threadIdx.x;
    for (int i = tid; i < 64 * 256; i += gridDim.x * blockDim.x) {
        int j = i >> 8, k = i & 255;
        float w = W1[k * 64 + j];
        __nv_bfloat16 h = __float2bfloat16(w);
        __nv_bfloat16 l = __float2bfloat16(w - __bfloat162float(h));
        int c = k >> 6, kk = k & 63;
        unsigned off = swz((unsigned)(j * 128 + kk * 2)) >> 1;
        g_W1s[c * 8192 + off] = h;
        g_W1s[c * 8192 + 4096 + off] = l;
    }
}

template <int LAYER>
__global__ void fold_kernel(const float* __restrict__ Wn, const float* __restrict__ bn,
                            const float* __restrict__ gamma, const float* __restrict__ beta,
                            float Einv) {
    __shared__ float s[64], t[64];
    int j = threadIdx.x;
    float mean = g_sum[LAYER][j] * Einv;
    float var  = g_sq[LAYER][j] * Einv - mean * mean;
    float sc = gamma[j] / sqrtf(var + BN_EPS);
    s[j] = sc;
    t[j] = beta[j] - mean * sc;
    __syncthreads();
    __nv_bfloat16* Wd = (LAYER == 0) ? g_W2s : g_W3s;
    float* bO = (LAYER == 0) ? g_bf2 : g_bf3;
    float bacc = bn[j];
#pragma unroll
    for (int k = 0; k < 64; k++) {
        float w0 = Wn[k * 64 + j];
        float w = w0 * s[k];
        bacc += t[k] * w0;
        __nv_bfloat16 h = __float2bfloat16(w);
        __nv_bfloat16 l = __float2bfloat16(w - __bfloat162float(h));
        unsigned off = swz((unsigned)(j * 128 + k * 2)) >> 1;
        Wd[off] = h;
        Wd[4096 + off] = l;
    }
    bO[j] = bacc;
}

__global__ void fin_kernel(const float* __restrict__ gamma, const float* __restrict__ beta,
                           float Einv) {
    int j = threadIdx.x;
    float mean = g_sum[2][j] * Einv;
    float var  = g_sq[2][j] * Einv - mean * mean;
    float sc = gamma[j] / sqrtf(var + BN_EPS);
    g_s3[j] = sc;
    g_t3[j] = beta[j] - mean * sc;
}

__global__ void affine_kernel(float* __restrict__ out, int n4) {
    __shared__ float s[64], t[64];
    if (threadIdx.x < 64) { s[threadIdx.x] = g_s3[threadIdx.x]; t[threadIdx.x] = g_t3[threadIdx.x]; }
    __syncthreads();
    float4* o4 = reinterpret_cast<float4*>(out);
    for (int i = blockIdx.x * blockDim.x + threadIdx.x; i < n4; i += gridDim.x * blockDim.x) {
        float4 v = o4[i];
        int fb = (i & 15) << 2;
        v.x = v.x * s[fb] + t[fb];
        v.y = v.y * s[fb + 1] + t[fb + 1];
        v.z = v.z * s[fb + 2] + t[fb + 2];
        v.w = v.w * s[fb + 3] + t[fb + 3];
        o4[i] = v;
    }
}

// ---- persistent HMMA layer ----
// 128 threads/block; each block loops over 128-edge tiles (stride = grid).
// W staged once. A double-buffered via cp.async. Stats in registers.
// smem: NCH==1: [W 16K][A: 2 x (hi16K+lo16K)] = 80K  (2 blocks/SM)
//       NCH==4: [W 64K][A hi16K+lo16K][F: 2 x 34,816B fp32 pitched] ~165K (1 block/SM)
template <int NCH, int LAYER>
__global__ void __launch_bounds__(128)
mma_layer(const float* __restrict__ in0, const float* __restrict__ in1,
          const float* __restrict__ in2, const float* __restrict__ ga,
          const void* __restrict__ batch, const float* __restrict__ bias1,
          float* __restrict__ outP, int E, int G) {
    extern __shared__ char dyn[];
    __shared__ float bs[64], ssum[64], ssq[64];
    unsigned dynb = smem_u32(dyn);
    unsigned ab = (dynb + 1023u) & ~1023u;
    char* abp = dyn + (ab - dynb);
    const unsigned aoff = NCH * 16384u;          // A region after W
    const unsigned foff = aoff + 32768u;         // F region (NCH==4)
    int tid = threadIdx.x, warp = tid >> 5, lane = tid & 31;

    if (tid < 64) {
        bs[tid] = ((LAYER == 0) ? bias1 : (LAYER == 1) ? g_bf2 : g_bf3)[tid];
        ssum[tid] = 0.f;
        ssq[tid] = 0.f;
    }
    // stage W once (group 1)
    {
        const char* ws = (LAYER == 0) ? (const char*)g_W1s
                       : (LAYER == 1) ? (const char*)g_W2s : (const char*)g_W3s;
        for (int i = tid; i < NCH * 1024; i += 128) cp16(ab + i * 16u, ws + (size_t)i * 16);
    }
    cp_commit();

    int nt = (E + 127) >> 7;
    int nb = gridDim.x;
    int t0 = blockIdx.x;

    float acc[2][8][4];
#pragma unroll
    for (int mi = 0; mi < 2; mi++)
#pragma unroll
        for (int q = 0; q < 8; q++)
#pragma unroll
            for (int u = 0; u < 4; u++) acc[mi][q][u] = 0.f;
    float ls[8][2], lq[8][2];
#pragma unroll
    for (int q = 0; q < 8; q++) { ls[q][0] = ls[q][1] = 0.f; lq[q][0] = lq[q][1] = 0.f; }

    // ldmatrix lane geometry (verified in R16)
    int m0 = warp * 32;
    int arr = lane & 15, akc = lane >> 4;
    int bnr = (lane & 7) + ((lane >> 4) << 3);
    int bkc = (lane >> 3) & 1;
    unsigned aA = ab + aoff;

    if (t0 < nt) {
        if (NCH == 1) {
            // ---- L2/L3: bf16 A, double-buffered tiles ----
            // prologue: stage tile t0 -> parity 0
            {
                int row = t0 * 128 + tid; if (row >= E) row = E - 1;
                const char* hs = (const char*)g_hh + (size_t)row * 128;
                const char* lsrc = (const char*)g_hl + (size_t)row * 128;
#pragma unroll
                for (int m = 0; m < 8; m++) {
                    unsigned so = swz((unsigned)(tid * 128 + m * 16));
                    cp16(aA + so, hs + m * 16);
                    cp16(aA + 16384u + so, lsrc + m * 16);
                }
            }
            cp_commit();
            int par = 0;
            for (int t = t0; t < nt; t += nb) {
                if (t + nb < nt) {
                    int row = (t + nb) * 128 + tid; if (row >= E) row = E - 1;
                    const char* hs = (const char*)g_hh + (size_t)row * 128;
                    const char* lsrc = (const char*)g_hl + (size_t)row * 128;
                    unsigned dst = aA + (unsigned)(par ^ 1) * 32768u;
#pragma unroll
                    for (int m = 0; m < 8; m++) {
                        unsigned so = swz((unsigned)(tid * 128 + m * 16));
                        cp16(dst + so, hs + m * 16);
                        cp16(dst + 16384u + so, lsrc + m * 16);
                    }
                    cp_commit();
                    cp_wait<1>();
                } else {
                    cp_wait<0>();
                }
                __syncthreads();
                unsigned aH = aA + (unsigned)par * 32768u, aL = aH + 16384u;
#pragma unroll
                for (int s = 0; s < 3; s++) {
                    unsigned abase = (s == 2) ? aL : aH;
                    unsigned wbase = ab + ((s == 1) ? 8192u : 0u);
#pragma unroll
                    for (int k = 0; k < 4; k++) {
                        unsigned a0[4], a1[4];
                        ldsm4(a0, abase + swz((unsigned)((m0 + arr) * 128 + k * 32 + akc * 16)));
                        ldsm4(a1, abase + swz((unsigned)((m0 + 16 + arr) * 128 + k * 32 + akc * 16)));
#pragma unroll
                        for (int np = 0; np < 4; np++) {
                            unsigned bf[4];
                            ldsm4(bf, wbase + swz((unsigned)((np * 16 + bnr) * 128 + k * 32 + bkc * 16)));
                            mma16816(acc[0][2 * np], a0, bf);
                            mma16816(acc[0][2 * np + 1], a0, bf + 2);
                            mma16816(acc[1][2 * np], a1, bf);
                            mma16816(acc[1][2 * np + 1], a1, bf + 2);
                        }
                    }
                }
                // epilogue: direct stores + reg stats, reset acc
                int e0 = t * 128;
#pragma unroll
                for (int mi = 0; mi < 2; mi++) {
                    int r = m0 + mi * 16 + (lane >> 2);
                    bool ok0 = (e0 + r) < E, ok1 = (e0 + r + 8) < E;
#pragma unroll
                    for (int q = 0; q < 8; q++) {
                        int cc = q * 8 + (lane & 3) * 2;
                        float v0 = fmaxf(acc[mi][q][0] + bs[cc], 0.f);
                        float v1 = fmaxf(acc[mi][q][1] + bs[cc + 1], 0.f);
                        float v2 = fmaxf(acc[mi][q][2] + bs[cc], 0.f);
                        float v3 = fmaxf(acc[mi][q][3] + bs[cc + 1], 0.f);
                        acc[mi][q][0] = acc[mi][q][1] = acc[mi][q][2] = acc[mi][q][3] = 0.f;
                        if (ok0) {
                            if (LAYER < 2) {
                                unsigned h = packbf(v0, v1);
                                unsigned l = packbf(v0 - __uint_as_float(h << 16),
                                                    v1 - __uint_as_float(h & 0xffff0000u));
                                *(unsigned*)((char*)g_hh + (size_t)(e0 + r) * 128 + cc * 2) = h;
                                *(unsigned*)((char*)g_hl + (size_t)(e0 + r) * 128 + cc * 2) = l;
                            } else {
                                *(float2*)(outP + (size_t)(e0 + r) * 64 + cc) = make_float2(v0, v1);
                            }
                            ls[q][0] += v0; ls[q][1] += v1;
                            lq[q][0] += v0 * v0; lq[q][1] += v1 * v1;
                        }
                        if (ok1) {
                            if (LAYER < 2) {
                                unsigned h = packbf(v2, v3);
                                unsigned l = packbf(v2 - __uint_as_float(h << 16),
                                                    v3 - __uint_as_float(h & 0xffff0000u));
                                *(unsigned*)((char*)g_hh + (size_t)(e0 + r + 8) * 128 + cc * 2) = h;
                                *(unsigned*)((char*)g_hl + (size_t)(e0 + r + 8) * 128 + cc * 2) = l;
                            } else {
                                *(float2*)(outP + (size_t)(e0 + r + 8) * 64 + cc) = make_float2(v2, v3);
                            }
                            ls[q][0] += v2; ls[q][1] += v3;
                            lq[q][0] += v2 * v2; lq[q][1] += v3 * v3;
                        }
                    }
                }
                __syncthreads();   // A[par] reads done before restage
                par ^= 1;
            }
        } else {
            // ---- L1: fp32 chunks cp.async -> F (pitched) -> convert -> A ----
            const unsigned FP = 272u;              // fp32 row pitch bytes (68 floats)
            const unsigned FSZ = 128u * FP;        // 34,816 per parity
            // prologue: stage (t0, chunk0) -> F parity 0
            {
                int row = t0 * 128 + tid; if (row >= E) row = E - 1;
                const float4* s4 = (const float4*)(in0 + (size_t)row * 64);
                unsigned fd = ab + foff + tid * FP;
#pragma unroll
                for (int m = 0; m < 16; m++) cp16(fd + m * 16u, s4 + m);
            }
            cp_commit();
            int par = 0;
            for (int t = t0; t < nt; t += nb) {
#pragma unroll 1
                for (int c = 0; c < 4; c++) {
                    int tn = (c < 3) ? t : t + nb;
                    int cn = (c < 3) ? c + 1 : 0;
                    bool hn = (tn < nt);
                    if (hn) {
                        int row = tn * 128 + tid; if (row >= E) row = E - 1;
                        const float* sp;
                        if (cn == 3) sp = ga + (size_t)load_bidx(batch, row, G) * 64;
                        else sp = ((cn == 0) ? in0 : (cn == 1) ? in1 : in2) + (size_t)row * 64;
                        const float4* s4 = (const float4*)sp;
                        unsigned fd = ab + foff + (unsigned)(par ^ 1) * FSZ + tid * FP;
#pragma unroll
                        for (int m = 0; m < 16; m++) cp16(fd + m * 16u, s4 + m);
                        cp_commit();
                        cp_wait<1>();
                    } else {
                        cp_wait<0>();
                    }
                    __syncthreads();   // F[par] ready; prev MMA reads of A done
                    // convert F[par] row tid -> A (hi/lo, swizzled)
                    {
                        const float4* fr = (const float4*)(abp + foff + (unsigned)par * FSZ + tid * FP);
#pragma unroll
                        for (int g = 0; g < 8; g++) {
                            float4 p0 = fr[2 * g], p1 = fr[2 * g + 1];
                            unsigned h0 = packbf(p0.x, p0.y), h1 = packbf(p0.z, p0.w);
                            unsigned h2 = packbf(p1.x, p1.y), h3 = packbf(p1.z, p1.w);
                            uint4 hv = make_uint4(h0, h1, h2, h3);
                            uint4 lv = make_uint4(
                                packbf(p0.x - __uint_as_float(h0 << 16), p0.y - __uint_as_float(h0 & 0xffff0000u)),
                                packbf(p0.z - __uint_as_float(h1 << 16), p0.w - __uint_as_float(h1 & 0xffff0000u)),
                                packbf(p1.x - __uint_as_float(h2 << 16), p1.y - __uint_as_float(h2 & 0xffff0000u)),
                                packbf(p1.z - __uint_as_float(h3 << 16), p1.w - __uint_as_float(h3 & 0xffff0000u)));
                            unsigned so = swz((unsigned)(tid * 128 + g * 16));
                            *(uint4*)(abp + aoff + so) = hv;
                            *(uint4*)(abp + aoff + 16384u + so) = lv;
                        }
                    }
                    __syncthreads();
                    unsigned wb = ab + (unsigned)c * 16384u;
#pragma unroll
                    for (int s2 = 0; s2 < 3; s2++) {
                        unsigned abase = (s2 == 2) ? (aA + 16384u) : aA;
                        unsigned wbase = wb + ((s2 == 1) ? 8192u : 0u);
#pragma unroll
                        for (int k = 0; k < 4; k++) {
                            unsigned a0[4], a1[4];
                            ldsm4(a0, abase + swz((unsigned)((m0 + arr) * 128 + k * 32 + akc * 16)));
                            ldsm4(a1, abase + swz((unsigned)((m0 + 16 + arr) * 128 + k * 32 + akc * 16)));
#pragma unroll
                            for (int np = 0; np < 4; np++) {
                                unsigned bf[4];
                                ldsm4(bf, wbase + swz((unsigned)((np * 16 + bnr) * 128 + k * 32 + bkc * 16)));
                                mma16816(acc[0][2 * np], a0, bf);
                                mma16816(acc[0][2 * np + 1], a0, bf + 2);
                                mma16816(acc[1][2 * np], a1, bf);
                                mma16816(acc[1][2 * np + 1], a1, bf + 2);
                            }
                        }
                    }
                    par ^= 1;
                }
                // epilogue for tile t (stores to g_hh/g_hl + reg stats, reset acc)
                int e0 = t * 128;
#pragma unroll
                for (int mi = 0; mi < 2; mi++) {
                    int r = m0 + mi * 16 + (lane >> 2);
                    bool ok0 = (e0 + r) < E, ok1 = (e0 + r + 8) < E;
#pragma unroll
                    for (int q = 0; q < 8; q++) {
                        int cc = q * 8 + (lane & 3) * 2;
                        float v0 = fmaxf(acc[mi][q][0] + bs[cc], 0.f);
                        float v1 = fmaxf(acc[mi][q][1] + bs[cc + 1], 0.f);
                        float v2 = fmaxf(acc[mi][q][2] + bs[cc], 0.f);
                        float v3 = fmaxf(acc[mi][q][3] + bs[cc + 1], 0.f);
                        acc[mi][q][0] = acc[mi][q][1] = acc[mi][q][2] = acc[mi][q][3] = 0.f;
                        if (ok0) {
                            unsigned h = packbf(v0, v1);
                            unsigned l = packbf(v0 - __uint_as_float(h << 16),
                                                v1 - __uint_as_float(h & 0xffff0000u));
                            *(unsigned*)((char*)g_hh + (size_t)(e0 + r) * 128 + cc * 2) = h;
                            *(unsigned*)((char*)g_hl + (size_t)(e0 + r) * 128 + cc * 2) = l;
                            ls[q][0] += v0; ls[q][1] += v1;
                            lq[q][0] += v0 * v0; lq[q][1] += v1 * v1;
                        }
                        if (ok1) {
                            unsigned h = packbf(v2, v3);
                            unsigned l = packbf(v2 - __uint_as_float(h << 16),
                                                v3 - __uint_as_float(h & 0xffff0000u));
                            *(unsigned*)((char*)g_hh + (size_t)(e0 + r + 8) * 128 + cc * 2) = h;
                            *(unsigned*)((char*)g_hl + (size_t)(e0 + r + 8) * 128 + cc * 2) = l;
                            ls[q][0] += v2; ls[q][1] += v3;
                            lq[q][0] += v2 * v2; lq[q][1] += v3 * v3;
                        }
                    }
                }
            }
        }
    }

    // ---- stats: shfl-reduce over row lanes (bits 2..4), smem, then global ----
#pragma unroll
    for (int q = 0; q < 8; q++) {
#pragma unroll
        for (int u = 0; u < 2; u++) {
            ls[q][u] += __shfl_xor_sync(0xffffffffu, ls[q][u], 4);
            ls[q][u] += __shfl_xor_sync(0xffffffffu, ls[q][u], 8);
            ls[q][u] += __shfl_xor_sync(0xffffffffu, ls[q][u], 16);
            lq[q][u] += __shfl_xor_sync(0xffffffffu, lq[q][u], 4);
            lq[q][u] += __shfl_xor_sync(0xffffffffu, lq[q][u], 8);
            lq[q][u] += __shfl_xor_sync(0xffffffffu, lq[q][u], 16);
        }
    }
    __syncthreads();   // ssum/ssq initialized; also all prior use done
    if (lane < 4) {
#pragma unroll
        for (int q = 0; q < 8; q++) {
            int cc = q * 8 + lane * 2;
            atomicAdd(&ssum[cc], ls[q][0]);
            atomicAdd(&ssum[cc + 1], ls[q][1]);
            atomicAdd(&ssq[cc], lq[q][0]);
            atomicAdd(&ssq[cc + 1], lq[q][1]);
        }
    }
    __syncthreads();
    if (tid < 64) {
        atomicAdd(&g_sum[LAYER][tid], ssum[tid]);
        atomicAdd(&g_sq[LAYER][tid], ssq[tid]);
    }
}

extern "C" void kernel_launch(void* const* d_in, const int* in_sizes, int n_in,
                              void* d_out, int out_size) {
    const float* src = (const float*)d_in[0];
    const float* dst = (const float*)d_in[1];
    const float* eat = (const float*)d_in[2];
    const float* gat = (const float*)d_in[3];
    const void*  batch = d_in[4];
    const float* W1 = (const float*)d_in[5];
    const float* b1 = (const float*)d_in[6];
    const float* W2 = (const float*)d_in[7];
    const float* b2 = (const float*)d_in[8];
    const float* W3 = (const float*)d_in[9];
    const float* b3 = (const float*)d_in[10];
    const float* g1 = (const float*)d_in[11];
    const float* be1 = (const float*)d_in[12];
    const float* g2 = (const float*)d_in[13];
    const float* be2 = (const float*)d_in[14];
    const float* g3 = (const float*)d_in[15];
    const float* be3 = (const float*)d_in[16];

    int E = in_sizes[0] / 64;
    int G = in_sizes[3] / 64;
    float Einv = 1.0f / (float)E;
    float* out = (float*)d_out;
    int nt = (E + 127) >> 7;

    int nsm = 148;
    cudaDeviceGetAttribute(&nsm, cudaDevAttrMultiProcessorCount, 0);
    if (nsm < 1) nsm = 148;
    int nb1 = (nsm < nt) ? nsm : nt;                 // L1: 1 block/SM
    int nbn = (2 * nsm < nt) ? 2 * nsm : nt;         // L2/3: 2 blocks/SM

    const int SM1 = 65536 + 32768 + 2 * 34816 + 1024;  // 168,960
    const int SMN = 16384 + 65536 + 1024;              // 82,944
    cudaFuncSetAttribute(mma_layer<4, 0>, cudaFuncAttributeMaxDynamicSharedMemorySize, SM1);
    cudaFuncSetAttribute(mma_layer<1, 1>, cudaFuncAttributeMaxDynamicSharedMemorySize, SMN);
    cudaFuncSetAttribute(mma_layer<1, 2>, cudaFuncAttributeMaxDynamicSharedMemorySize, SMN);

    prep_kernel<<<16, 256>>>(W1, batch, E, G);

    // L1: concat @ W1 + b1 -> relu -> hh/hl, stats[0]
    mma_layer<4, 0><<<nb1, 128, SM1>>>(src, dst, eat, gat, batch, b1, out, E, G);
    fold_kernel<0><<<1, 64>>>(W2, b2, g1, be1, Einv);

    // L2: h @ W2' + b2' -> relu -> hh/hl, stats[1]
    mma_layer<1, 1><<<nbn, 128, SMN>>>(src, dst, eat, gat, batch, b1, out, E, G);
    fold_kernel<1><<<1, 64>>>(W3, b3, g2, be2, Einv);

    // L3: h @ W3' + b3' -> relu -> d_out (pre-BN), stats[2]
    mma_layer<1, 2><<<nbn, 128, SMN>>>(src, dst, eat, gat, batch, b1, out, E, G);
    fin_kernel<<<1, 64>>>(g3, be3, Einv);

    affine_kernel<<<4096, 256>>>(out, E * 16);
}